// round 5
// baseline (speedup 1.0000x reference)
#include <cuda_runtime.h>
#include <cuda_bf16.h>
#include <math.h>

// ---------------------------------------------------------------------------
// DCNv2: B=8, C=64, H=W=128, K=3, O=64
//   k0: transpose w_dcn (O,C,3,3) -> wT[k][c][o]
//   k1: offset(18ch)+mask(9ch) 3x3 conv over x, sigmoid on mask, to scratch
//   k2: per-pixel deformable bilinear sample + 576x64 GEMV with SMEM weights
// All fp32; inner products use packed fma.rn.f32x2 (2 FMA / instr).
// ---------------------------------------------------------------------------

#define Bb 8
#define Cc 64
#define Hh 128
#define Ww 128
#define HW (Hh*Ww)
#define K2 9
#define Oo 64

// scratch (static __device__ arrays: allocation-free per harness rules)
__device__ float g_off [Bb * 18 * HW];   // (b, 2k{dy,dx}, h, w)
__device__ float g_mask[Bb * 9  * HW];   // sigmoid already applied
__device__ float g_wT  [K2 * Cc * Oo];   // [k][c][o]

// ---- packed f32x2 helpers --------------------------------------------------
__device__ __forceinline__ unsigned long long pk2(float lo, float hi) {
    unsigned long long r;
    asm("mov.b64 %0, {%1, %2};" : "=l"(r) : "f"(lo), "f"(hi));
    return r;
}
__device__ __forceinline__ void upk2(unsigned long long v, float& lo, float& hi) {
    asm("mov.b64 {%0, %1}, %2;" : "=f"(lo), "=f"(hi) : "l"(v));
}
__device__ __forceinline__ unsigned long long fma2(unsigned long long a,
                                                   unsigned long long b,
                                                   unsigned long long c) {
    unsigned long long d;
    asm("fma.rn.f32x2 %0, %1, %2, %3;" : "=l"(d) : "l"(a), "l"(b), "l"(c));
    return d;
}

// ---- k0: weight transpose --------------------------------------------------
__global__ void k_transpose(const float* __restrict__ w_dcn) {
    int i = blockIdx.x * 256 + threadIdx.x;
    if (i < K2 * Cc * Oo) {
        int k = i >> 12;            // /4096
        int c = (i >> 6) & 63;
        int o = i & 63;
        g_wT[i] = w_dcn[((o << 6) + c) * 9 + k];
    }
}

// ---- k1: offset + mask conv (64 -> 27 channels, 3x3, pad 1) ----------------
// grid: 512 blocks (b * 64 tiles of 16x16), 256 threads (one pixel each)
// smem: x tile 64 x 18 x 18 floats (82944B) + weights 64*9*28 floats (64512B)
#define T1_XTILE (64 * 324)
#define T1_WSZ   (64 * 9 * 28)
#define SMEM1    ((T1_XTILE + T1_WSZ) * 4)

__global__ __launch_bounds__(256, 1)
void k_offmask(const float* __restrict__ x,
               const float* __restrict__ w_off, const float* __restrict__ b_off,
               const float* __restrict__ w_mask, const float* __restrict__ b_mask) {
    extern __shared__ float sm1[];
    float* sx = sm1;             // [c][18][18]
    float* sw = sm1 + T1_XTILE;  // [(c*9+t)*28 + ch], ch: 0..17 off, 18..26 mask, 27 pad

    const int tid  = threadIdx.x;
    const int blk  = blockIdx.x;
    const int b    = blk >> 6;
    const int tile = blk & 63;
    const int tileY = tile >> 3, tileX = tile & 7;
    const int h0 = tileY * 16 - 1, w0 = tileX * 16 - 1;
    const float* xb = x + (b << 20);   // b*64*16384

    // load x tile (zero-padded halo)
    for (int i = tid; i < T1_XTILE; i += 256) {
        int c = i / 324; int rem = i - c * 324;
        int r = rem / 18; int cc = rem - r * 18;
        int gy = h0 + r, gx = w0 + cc;
        float v = 0.f;
        if ((unsigned)gy < 128u && (unsigned)gx < 128u)
            v = xb[(c << 14) + (gy << 7) + gx];
        sx[i] = v;
    }
    // load + rearrange weights
    for (int i = tid; i < T1_WSZ; i += 256) {
        int ch = i % 28; int ct = i / 28;
        int c = ct / 9;  int t = ct - c * 9;
        float v = 0.f;
        if (ch < 18)      v = w_off [(ch * 64 + c) * 9 + t];
        else if (ch < 27) v = w_mask[((ch - 18) * 64 + c) * 9 + t];
        sw[i] = v;
    }
    __syncthreads();

    const int ty = tid >> 4, tx = tid & 15;

    unsigned long long acc[14];
#pragma unroll
    for (int j = 0; j < 14; j++) {
        int c0 = 2 * j, c1 = 2 * j + 1;
        float lo = (c0 < 18) ? b_off[c0] : ((c0 < 27) ? b_mask[c0 - 18] : 0.f);
        float hi = (c1 < 18) ? b_off[c1] : ((c1 < 27) ? b_mask[c1 - 18] : 0.f);
        acc[j] = pk2(lo, hi);
    }

    for (int c = 0; c < 64; c++) {
        const float* tp = sx + c * 324 + ty * 18 + tx;
        float tv[9];
#pragma unroll
        for (int di = 0; di < 3; di++)
#pragma unroll
            for (int dj = 0; dj < 3; dj++)
                tv[di * 3 + dj] = tp[di * 18 + dj];
        const unsigned long long* wp =
            (const unsigned long long*)(sw + c * 9 * 28);
#pragma unroll
        for (int t = 0; t < 9; t++) {
            unsigned long long xv = pk2(tv[t], tv[t]);
#pragma unroll
            for (int j = 0; j < 14; j++)
                acc[j] = fma2(wp[t * 14 + j], xv, acc[j]);
        }
    }

    const int oh = tileY * 16 + ty, ow = tileX * 16 + tx;
    const int hw = (oh << 7) + ow;
#pragma unroll
    for (int j = 0; j < 14; j++) {
        float lo, hi; upk2(acc[j], lo, hi);
        int ch = 2 * j;
        if (ch < 18) g_off[(b * 18 + ch) * HW + hw] = lo;
        else         g_mask[(b * 9 + ch - 18) * HW + hw] = 1.f / (1.f + expf(-lo));
        ch++;
        if (ch < 18)      g_off[(b * 18 + ch) * HW + hw] = hi;
        else if (ch < 27) g_mask[(b * 9 + ch - 18) * HW + hw] = 1.f / (1.f + expf(-hi));
    }
}

// ---- k2: deformable sampling + GEMV ---------------------------------------
// grid: 512 blocks x 256 threads, one pixel per thread.
// smem: wT 9*64*64 floats = 147456B (broadcast LDS in inner loop)
#define SMEM2 (K2 * Cc * Oo * 4)

__global__ __launch_bounds__(256, 1)
void k_dcn(const float* __restrict__ x,
           const float* __restrict__ b_dcn,
           float* __restrict__ out) {
    extern __shared__ float sw2[];
    const int tid = threadIdx.x;
    for (int i = tid; i < K2 * Cc * Oo; i += 256) sw2[i] = g_wT[i];
    __syncthreads();

    const int pix = blockIdx.x * 256 + tid;
    const int b  = pix >> 14;
    const int hw = pix & 16383;
    const int h  = hw >> 7;
    const int w  = hw & 127;
    const float* xb = x + (b << 20);

    unsigned long long acc[32];
#pragma unroll
    for (int j = 0; j < 32; j++) acc[j] = pk2(b_dcn[2 * j], b_dcn[2 * j + 1]);

    const float* offp = g_off  + b * 18 * HW + hw;
    const float* mp   = g_mask + b * 9  * HW + hw;

#pragma unroll
    for (int k = 0; k < 9; k++) {
        const float dy = offp[(2 * k) << 14];
        const float dx = offp[(2 * k + 1) << 14];
        const float m  = mp[k << 14];
        const float py = (float)(h - 1 + (k / 3)) + dy;
        const float px = (float)(w - 1 + (k % 3)) + dx;
        const float y0f = floorf(py), x0f = floorf(px);
        const float wy1 = py - y0f, wx1 = px - x0f;
        const float wy0 = 1.f - wy1, wx0 = 1.f - wx1;
        const int y0 = (int)y0f, x0 = (int)x0f;
        const int y1 = y0 + 1,  x1 = x0 + 1;
        const float vy0 = ((unsigned)y0 < 128u) ? 1.f : 0.f;
        const float vy1 = ((unsigned)y1 < 128u) ? 1.f : 0.f;
        const float vx0 = ((unsigned)x0 < 128u) ? 1.f : 0.f;
        const float vx1 = ((unsigned)x1 < 128u) ? 1.f : 0.f;
        const int y0c = min(max(y0, 0), 127), y1c = min(max(y1, 0), 127);
        const int x0c = min(max(x0, 0), 127), x1c = min(max(x1, 0), 127);
        const float W00 = wy0 * wx0 * m * vy0 * vx0;
        const float W01 = wy0 * wx1 * m * vy0 * vx1;
        const float W10 = wy1 * wx0 * m * vy1 * vx0;
        const float W11 = wy1 * wx1 * m * vy1 * vx1;
        const int o00 = (y0c << 7) + x0c, o01 = (y0c << 7) + x1c;
        const int o10 = (y1c << 7) + x0c, o11 = (y1c << 7) + x1c;

        const unsigned long long* wk = (const unsigned long long*)(sw2 + (k << 12));
        const float* pc = xb;
#pragma unroll 4
        for (int c = 0; c < 64; c++) {
            const float s = W00 * pc[o00] + W01 * pc[o01]
                          + W10 * pc[o10] + W11 * pc[o11];
            const unsigned long long s2 = pk2(s, s);
            const unsigned long long* wr = wk + (c << 5);
#pragma unroll
            for (int j = 0; j < 32; j++) acc[j] = fma2(wr[j], s2, acc[j]);
            pc += HW;
        }
    }

    float* op = out + (b << 20) + hw;
#pragma unroll
    for (int j = 0; j < 32; j++) {
        float lo, hi; upk2(acc[j], lo, hi);
        op[(2 * j) << 14]     = lo;
        op[(2 * j + 1) << 14] = hi;
    }
}

// ---------------------------------------------------------------------------
extern "C" void kernel_launch(void* const* d_in, const int* in_sizes, int n_in,
                              void* d_out, int out_size) {
    const float* x      = (const float*)d_in[0];
    const float* w_off  = (const float*)d_in[1];
    const float* b_off  = (const float*)d_in[2];
    const float* w_mask = (const float*)d_in[3];
    const float* b_mask = (const float*)d_in[4];
    const float* w_dcn  = (const float*)d_in[5];
    const float* b_dcn  = (const float*)d_in[6];
    float* out = (float*)d_out;

    // opt-in to >48KB dynamic smem (idempotent host calls; not captured ops)
    cudaFuncSetAttribute(k_offmask, cudaFuncAttributeMaxDynamicSharedMemorySize, SMEM1);
    cudaFuncSetAttribute(k_dcn,     cudaFuncAttributeMaxDynamicSharedMemorySize, SMEM2);

    k_transpose<<<(K2 * Cc * Oo + 255) / 256, 256>>>(w_dcn);
    k_offmask<<<Bb * 64, 256, SMEM1>>>(x, w_off, b_off, w_mask, b_mask);
    k_dcn<<<Bb * HW / 256, 256, SMEM2>>>(x, b_dcn, out);
}

// round 8
// speedup vs baseline: 1.4310x; 1.4310x over previous
#include <cuda_runtime.h>
#include <cuda_bf16.h>
#include <math.h>

// ---------------------------------------------------------------------------
// DCNv2: B=8, C=64, H=W=128, K=3, O=64
//   k1 (k_offmask): 27-ch 3x3 conv (offsets+mask) in two 32-channel passes,
//                   + folded transpose of w_dcn -> g_wT[k][c][o]
//   k2 (k_dcn): per-row implicit GEMM: bilinear-sample S[64c x 128p] to smem,
//               register-tiled GEMM with W_k[64c x 64o] (8o x 4p per thread)
// All fp32; inner products use packed fma.rn.f32x2.
// ---------------------------------------------------------------------------

#define Bb 8
#define Cc 64
#define Hh 128
#define Ww 128
#define HW (Hh*Ww)
#define K2 9
#define Oo 64

__device__ float g_off [Bb * 18 * HW];   // (b, 2k{dy,dx}, h, w)
__device__ float g_mask[Bb * 9  * HW];   // sigmoid applied
__device__ float g_wT  [K2 * Cc * Oo];   // [k][c][o]

// ---- packed f32x2 helpers --------------------------------------------------
__device__ __forceinline__ unsigned long long pk2(float lo, float hi) {
    unsigned long long r;
    asm("mov.b64 %0, {%1, %2};" : "=l"(r) : "f"(lo), "f"(hi));
    return r;
}
__device__ __forceinline__ void upk2(unsigned long long v, float& lo, float& hi) {
    asm("mov.b64 {%0, %1}, %2;" : "=f"(lo), "=f"(hi) : "l"(v));
}
__device__ __forceinline__ unsigned long long fma2(unsigned long long a,
                                                   unsigned long long b,
                                                   unsigned long long c) {
    unsigned long long d;
    asm("fma.rn.f32x2 %0, %1, %2, %3;" : "=l"(d) : "l"(a), "l"(b), "l"(c));
    return d;
}

// ---- k1: offset + mask conv, two 32-channel passes -------------------------
// grid: 512 blocks (b * 64 tiles of 16x16), 256 threads (one pixel each)
// smem per pass: x tile 32 x 18 x 18 + weights 32*9*28  -> 73728 B (occ ~3)
#define T2_X (32 * 324)
#define T2_W (32 * 9 * 28)
#define SMEM1 ((T2_X + T2_W) * 4)

__global__ __launch_bounds__(256)
void k_offmask(const float* __restrict__ x,
               const float* __restrict__ w_off, const float* __restrict__ b_off,
               const float* __restrict__ w_mask, const float* __restrict__ b_mask,
               const float* __restrict__ w_dcn) {
    // folded transpose: blocks 0..143 write g_wT (consumed only by k_dcn,
    // which is stream-ordered after this kernel completes)
    {
        int gi = blockIdx.x * 256 + threadIdx.x;
        if (gi < K2 * Cc * Oo) {
            int k = gi >> 12;
            int c = (gi >> 6) & 63;
            int o = gi & 63;
            g_wT[gi] = w_dcn[((o << 6) + c) * 9 + k];
        }
    }

    extern __shared__ float sm1[];
    float* sx = sm1;           // [32][18][18]
    float* sw = sm1 + T2_X;    // [(c*9+t)*28 + ch]

    const int tid  = threadIdx.x;
    const int blk  = blockIdx.x;
    const int b    = blk >> 6;
    const int tile = blk & 63;
    const int tileY = tile >> 3, tileX = tile & 7;
    const int h0 = tileY * 16 - 1, w0 = tileX * 16 - 1;
    const float* xb = x + (b << 20);
    const int ty = tid >> 4, tx = tid & 15;

    unsigned long long acc[14];
#pragma unroll
    for (int j = 0; j < 14; j++) {
        int c0 = 2 * j, c1 = 2 * j + 1;
        float lo = (c0 < 18) ? b_off[c0] : ((c0 < 27) ? b_mask[c0 - 18] : 0.f);
        float hi = (c1 < 18) ? b_off[c1] : ((c1 < 27) ? b_mask[c1 - 18] : 0.f);
        acc[j] = pk2(lo, hi);
    }

#pragma unroll 1
    for (int cp = 0; cp < 2; cp++) {
        const int cbase = cp << 5;
        // stage x half-tile (zero-padded halo)
        for (int i = tid; i < T2_X; i += 256) {
            int c = i / 324; int rem = i - c * 324;
            int r = rem / 18; int cc = rem - r * 18;
            int gy = h0 + r, gx = w0 + cc;
            float v = 0.f;
            if ((unsigned)gy < 128u && (unsigned)gx < 128u)
                v = xb[((cbase + c) << 14) + (gy << 7) + gx];
            sx[i] = v;
        }
        // stage weight half
        for (int i = tid; i < T2_W; i += 256) {
            int ch = i % 28; int ct = i / 28;
            int c = ct / 9;  int t = ct - c * 9;
            float v = 0.f;
            if (ch < 18)      v = w_off [(ch * 64 + cbase + c) * 9 + t];
            else if (ch < 27) v = w_mask[((ch - 18) * 64 + cbase + c) * 9 + t];
            sw[i] = v;
        }
        __syncthreads();

        for (int c = 0; c < 32; c++) {
            const float* tp = sx + c * 324 + ty * 18 + tx;
            float tv[9];
#pragma unroll
            for (int di = 0; di < 3; di++)
#pragma unroll
                for (int dj = 0; dj < 3; dj++)
                    tv[di * 3 + dj] = tp[di * 18 + dj];
            const unsigned long long* wp =
                (const unsigned long long*)(sw + c * 9 * 28);
#pragma unroll
            for (int t = 0; t < 9; t++) {
                unsigned long long xv = pk2(tv[t], tv[t]);
#pragma unroll
                for (int j = 0; j < 14; j++)
                    acc[j] = fma2(wp[t * 14 + j], xv, acc[j]);
            }
        }
        __syncthreads();
    }

    const int oh = tileY * 16 + ty, ow = tileX * 16 + tx;
    const int hw = (oh << 7) + ow;
#pragma unroll
    for (int j = 0; j < 14; j++) {
        float lo, hi; upk2(acc[j], lo, hi);
        int ch = 2 * j;
        if (ch < 18) g_off[(b * 18 + ch) * HW + hw] = lo;
        else         g_mask[(b * 9 + ch - 18) * HW + hw] = 1.f / (1.f + expf(-lo));
        ch++;
        if (ch < 18)      g_off[(b * 18 + ch) * HW + hw] = hi;
        else if (ch < 27) g_mask[(b * 9 + ch - 18) * HW + hw] = 1.f / (1.f + expf(-hi));
    }
}

// ---- k2: implicit-GEMM deformable conv -------------------------------------
// grid: 1024 blocks (b * 128 rows), 256 threads
// smem: Wk[64c][64o] 16KB + S[64c][128p] 32KB + params 4KB = 53248 B
#define SMEM2 (13312 * 4)

__global__ __launch_bounds__(256)
void k_dcn(const float* __restrict__ x,
           const float* __restrict__ b_dcn,
           float* __restrict__ out) {
    extern __shared__ float sm[];
    float* Wk = sm;                       // [64][64]
    float* S  = sm + 4096;                // [64][128]
    float* sW = sm + 12288;               // [128][4] bilinear weights (premul mask)
    int*   sO = (int*)(sm + 12800);       // [128][4] corner offsets

    const int tid = threadIdx.x;
    const int blk = blockIdx.x;           // = b*128 + h
    const int b = blk >> 7;
    const int h = blk & 127;
    const int hw0 = h << 7;
    const float* xb = x + (b << 20);

    // GEMM thread tile: 8 outputs x 4 pixels
    const int po = tid & 31, og = tid >> 5;
    const int p0 = po << 2, o0 = og << 3;

    unsigned long long acc[16];           // [o-pair 0..3][p 0..3]
#pragma unroll
    for (int i = 0; i < 4; i++)
#pragma unroll
        for (int j = 0; j < 4; j++)
            acc[i * 4 + j] = pk2(b_dcn[o0 + 2 * i], b_dcn[o0 + 2 * i + 1]);

    const int ps = tid & 127;             // sampling pixel
    const int c0 = tid >> 7;              // sampling channel phase (0/1)

#pragma unroll 1
    for (int k = 0; k < 9; k++) {
        // --- bilinear params for this tap, one pixel per thread (0..127) ---
        if (tid < 128) {
            const int p = tid;
            const float dy = g_off[(b * 18 + 2 * k) * HW + hw0 + p];
            const float dx = g_off[(b * 18 + 2 * k + 1) * HW + hw0 + p];
            const float m  = g_mask[(b * 9 + k) * HW + hw0 + p];
            const float py = (float)(h - 1 + k / 3) + dy;
            const float px = (float)(p - 1 + k % 3) + dx;
            const float y0f = floorf(py), x0f = floorf(px);
            const float wy1 = py - y0f, wx1 = px - x0f;
            const float wy0 = 1.f - wy1, wx0 = 1.f - wx1;
            const int y0 = (int)y0f, x0 = (int)x0f;
            const int y1 = y0 + 1,  x1 = x0 + 1;
            const float vy0 = ((unsigned)y0 < 128u) ? 1.f : 0.f;
            const float vy1 = ((unsigned)y1 < 128u) ? 1.f : 0.f;
            const float vx0 = ((unsigned)x0 < 128u) ? 1.f : 0.f;
            const float vx1 = ((unsigned)x1 < 128u) ? 1.f : 0.f;
            const int y0c = min(max(y0, 0), 127), y1c = min(max(y1, 0), 127);
            const int x0c = min(max(x0, 0), 127), x1c = min(max(x1, 0), 127);
            ((float4*)sW)[p] = make_float4(wy0 * wx0 * m * vy0 * vx0,
                                           wy0 * wx1 * m * vy0 * vx1,
                                           wy1 * wx0 * m * vy1 * vx0,
                                           wy1 * wx1 * m * vy1 * vx1);
            ((int4*)sO)[p] = make_int4((y0c << 7) + x0c, (y0c << 7) + x1c,
                                       (y1c << 7) + x0c, (y1c << 7) + x1c);
        }
        // --- stage Wk (16KB) ---
        {
            const float4* src = (const float4*)(g_wT + (k << 12));
            float4* dst = (float4*)Wk;
#pragma unroll
            for (int i = 0; i < 4; i++)
                dst[tid + 256 * i] = src[tid + 256 * i];
        }
        __syncthreads();

        // --- sample S[64][128]: thread keeps pixel ps, walks channels ---
        {
            const float4 Wp = ((const float4*)sW)[ps];
            const int4   Op = ((const int4*)sO)[ps];
            const float* pc = xb + (c0 << 14);
            float* Sp = S + (c0 << 7) + ps;
#pragma unroll 8
            for (int c = c0; c < 64; c += 2) {
                *Sp = Wp.x * pc[Op.x] + Wp.y * pc[Op.y]
                    + Wp.z * pc[Op.z] + Wp.w * pc[Op.w];
                pc += 2 * HW;
                Sp += 256;
            }
        }
        __syncthreads();

        // --- GEMM: acc[8o x 4p] += Wk[c][o]^T * S[c][p] ---
        {
            const float* wp = Wk + o0;
            const float* sp = S + p0;
#pragma unroll 8
            for (int c = 0; c < 64; c++) {
                const float4 wa = *(const float4*)(wp);
                const float4 wb = *(const float4*)(wp + 4);
                const float4 sv = *(const float4*)(sp);
                const unsigned long long w01 = pk2(wa.x, wa.y);
                const unsigned long long w23 = pk2(wa.z, wa.w);
                const unsigned long long w45 = pk2(wb.x, wb.y);
                const unsigned long long w67 = pk2(wb.z, wb.w);
                const unsigned long long s0 = pk2(sv.x, sv.x);
                const unsigned long long s1 = pk2(sv.y, sv.y);
                const unsigned long long s2 = pk2(sv.z, sv.z);
                const unsigned long long s3 = pk2(sv.w, sv.w);
                acc[0]  = fma2(w01, s0, acc[0]);
                acc[1]  = fma2(w01, s1, acc[1]);
                acc[2]  = fma2(w01, s2, acc[2]);
                acc[3]  = fma2(w01, s3, acc[3]);
                acc[4]  = fma2(w23, s0, acc[4]);
                acc[5]  = fma2(w23, s1, acc[5]);
                acc[6]  = fma2(w23, s2, acc[6]);
                acc[7]  = fma2(w23, s3, acc[7]);
                acc[8]  = fma2(w45, s0, acc[8]);
                acc[9]  = fma2(w45, s1, acc[9]);
                acc[10] = fma2(w45, s2, acc[10]);
                acc[11] = fma2(w45, s3, acc[11]);
                acc[12] = fma2(w67, s0, acc[12]);
                acc[13] = fma2(w67, s1, acc[13]);
                acc[14] = fma2(w67, s2, acc[14]);
                acc[15] = fma2(w67, s3, acc[15]);
                wp += 64;
                sp += 128;
            }
        }
        __syncthreads();
    }

    // --- epilogue: unpack o-pairs, vectorized stores (4 consecutive p) ---
    float* ob = out + (b << 20) + hw0 + p0;
#pragma unroll
    for (int i = 0; i < 4; i++) {
        float e0, d0, e1, d1, e2, d2, e3, d3;
        upk2(acc[i * 4 + 0], e0, d0);
        upk2(acc[i * 4 + 1], e1, d1);
        upk2(acc[i * 4 + 2], e2, d2);
        upk2(acc[i * 4 + 3], e3, d3);
        *(float4*)(ob + ((o0 + 2 * i) << 14))     = make_float4(e0, e1, e2, e3);
        *(float4*)(ob + ((o0 + 2 * i + 1) << 14)) = make_float4(d0, d1, d2, d3);
    }
}

// ---------------------------------------------------------------------------
extern "C" void kernel_launch(void* const* d_in, const int* in_sizes, int n_in,
                              void* d_out, int out_size) {
    const float* x      = (const float*)d_in[0];
    const float* w_off  = (const float*)d_in[1];
    const float* b_off  = (const float*)d_in[2];
    const float* w_mask = (const float*)d_in[3];
    const float* b_mask = (const float*)d_in[4];
    const float* w_dcn  = (const float*)d_in[5];
    const float* b_dcn  = (const float*)d_in[6];
    float* out = (float*)d_out;

    cudaFuncSetAttribute(k_offmask, cudaFuncAttributeMaxDynamicSharedMemorySize, SMEM1);
    cudaFuncSetAttribute(k_dcn,     cudaFuncAttributeMaxDynamicSharedMemorySize, SMEM2);

    k_offmask<<<Bb * 64, 256, SMEM1>>>(x, w_off, b_off, w_mask, b_mask, w_dcn);
    k_dcn<<<Bb * Hh, 256, SMEM2>>>(x, b_dcn, out);
}

// round 11
// speedup vs baseline: 1.5502x; 1.0833x over previous
#include <cuda_runtime.h>
#include <cuda_bf16.h>
#include <math.h>
#include <stdint.h>

// ---------------------------------------------------------------------------
// DCNv2: B=8, C=64, H=W=128, K=3, O=64
//  k_offmask: 27-ch 3x3 conv (offsets+mask), 2 y-pixels per thread,
//             + folded bf16 hi/lo split + SW128 byte-swizzle of w_dcn.
//  k_dcn:     per-row GEMM on mma.sync (HMMA, valid on plain sm_103):
//             sample S[128p x 64c] fp32 -> bf16 hi/lo swizzled tiles in SMEM;
//             ldmatrix + m16n8k16 bf16 MMAs, fp32 accum in registers.
// ---------------------------------------------------------------------------

#define Bb 8
#define Cc 64
#define HW (128*128)
#define K2 9

__device__ float g_off [Bb * 18 * HW];
__device__ float g_mask[Bb * 9  * HW];
__device__ __align__(16) unsigned g_Bhi[K2 * 2048];  // [k][swz(o*128+c*2)>>2]
__device__ __align__(16) unsigned g_Blo[K2 * 2048];

// ---- packed f32x2 helpers ---------------------------------------------------
__device__ __forceinline__ unsigned long long pk2(float lo, float hi) {
    unsigned long long r;
    asm("mov.b64 %0, {%1, %2};" : "=l"(r) : "f"(lo), "f"(hi));
    return r;
}
__device__ __forceinline__ void upk2(unsigned long long v, float& lo, float& hi) {
    asm("mov.b64 {%0, %1}, %2;" : "=f"(lo), "=f"(hi) : "l"(v));
}
__device__ __forceinline__ unsigned long long fma2(unsigned long long a,
                                                   unsigned long long b,
                                                   unsigned long long c) {
    unsigned long long d;
    asm("fma.rn.f32x2 %0, %1, %2, %3;" : "=l"(d) : "l"(a), "l"(b), "l"(c));
    return d;
}

// ---- warp MMA helpers (plain sm_103-legal) ----------------------------------
__device__ __forceinline__ unsigned smem_u32(const void* p) {
    unsigned a;
    asm("{ .reg .u64 t; cvta.to.shared.u64 t, %1; cvt.u32.u64 %0, t; }"
        : "=r"(a) : "l"(p));
    return a;
}
__device__ __forceinline__ void ldx4(unsigned* r, unsigned addr) {
    asm volatile("ldmatrix.sync.aligned.m8n8.x4.shared.b16 {%0,%1,%2,%3}, [%4];"
                 : "=r"(r[0]), "=r"(r[1]), "=r"(r[2]), "=r"(r[3]) : "r"(addr));
}
__device__ __forceinline__ void ldx2(unsigned& r0, unsigned& r1, unsigned addr) {
    asm volatile("ldmatrix.sync.aligned.m8n8.x2.shared.b16 {%0,%1}, [%2];"
                 : "=r"(r0), "=r"(r1) : "r"(addr));
}
__device__ __forceinline__ void mma_bf16(float* c, const unsigned* a,
                                         unsigned b0, unsigned b1) {
    asm volatile("mma.sync.aligned.m16n8k16.row.col.f32.bf16.bf16.f32 "
                 "{%0,%1,%2,%3}, {%4,%5,%6,%7}, {%8,%9}, {%0,%1,%2,%3};"
                 : "+f"(c[0]), "+f"(c[1]), "+f"(c[2]), "+f"(c[3])
                 : "r"(a[0]), "r"(a[1]), "r"(a[2]), "r"(a[3]), "r"(b0), "r"(b1));
}
__device__ __forceinline__ int swz(int off) { return off ^ ((off >> 3) & 0x70); }

// ---- k_offmask: 27-ch 3x3 conv, 2 y-pixels per thread ----------------------
// grid: 512 (b*64 tiles of 16x16), 128 threads (tx 0..15, typ 0..7)
#define T2_X (32 * 324)
#define T2_W (32 * 9 * 28)
#define SMEM1 ((T2_X + T2_W) * 4)

__global__ __launch_bounds__(128)
void k_offmask(const float* __restrict__ x,
               const float* __restrict__ w_off, const float* __restrict__ b_off,
               const float* __restrict__ w_mask, const float* __restrict__ b_mask,
               const float* __restrict__ w_dcn) {
    const int tid = threadIdx.x;
    // folded prep: bf16 hi/lo split + byte-swizzle of w_dcn (blocks 0..143)
    {
        int gi = blockIdx.x * 128 + tid;
        if (gi < K2 * 64 * 32) {
            int k = gi >> 11;
            int rem = gi & 2047;
            int o = rem >> 5, c = (rem & 31) << 1;
            float v0 = w_dcn[((o << 6) + c) * 9 + k];
            float v1 = w_dcn[((o << 6) + c + 1) * 9 + k];
            __nv_bfloat16 h0 = __float2bfloat16(v0), h1 = __float2bfloat16(v1);
            __nv_bfloat16 l0 = __float2bfloat16(v0 - __bfloat162float(h0));
            __nv_bfloat16 l1 = __float2bfloat16(v1 - __bfloat162float(h1));
            int idx = swz((o << 7) + (c << 1)) >> 2;
            g_Bhi[(k << 11) + idx] = ((unsigned)__bfloat16_as_ushort(h1) << 16)
                                   | __bfloat16_as_ushort(h0);
            g_Blo[(k << 11) + idx] = ((unsigned)__bfloat16_as_ushort(l1) << 16)
                                   | __bfloat16_as_ushort(l0);
        }
    }

    extern __shared__ float sm1[];
    float* sx = sm1;           // [32][18][18]
    float* sw = sm1 + T2_X;    // [(c*9+t)*28 + ch]

    const int blk  = blockIdx.x;
    const int b    = blk >> 6;
    const int tile = blk & 63;
    const int tileY = tile >> 3, tileX = tile & 7;
    const int h0 = tileY * 16 - 1, w0 = tileX * 16 - 1;
    const float* xb = x + (b << 20);
    const int tx = tid & 15, typ = tid >> 4;

    unsigned long long acc0[14], acc1[14];
#pragma unroll
    for (int j = 0; j < 14; j++) {
        int c0 = 2 * j, c1 = 2 * j + 1;
        float lo = (c0 < 18) ? b_off[c0] : ((c0 < 27) ? b_mask[c0 - 18] : 0.f);
        float hi = (c1 < 18) ? b_off[c1] : ((c1 < 27) ? b_mask[c1 - 18] : 0.f);
        acc0[j] = pk2(lo, hi);
        acc1[j] = acc0[j];
    }

#pragma unroll 1
    for (int cp = 0; cp < 2; cp++) {
        const int cbase = cp << 5;
        for (int i = tid; i < T2_X; i += 128) {
            int c = i / 324; int rem = i - c * 324;
            int r = rem / 18; int cc = rem - r * 18;
            int gy = h0 + r, gx = w0 + cc;
            float v = 0.f;
            if ((unsigned)gy < 128u && (unsigned)gx < 128u)
                v = xb[((cbase + c) << 14) + (gy << 7) + gx];
            sx[i] = v;
        }
        for (int i = tid; i < T2_W; i += 128) {
            int ch = i % 28; int ct = i / 28;
            int c = ct / 9;  int t = ct - c * 9;
            float v = 0.f;
            if (ch < 18)      v = w_off [(ch * 64 + cbase + c) * 9 + t];
            else if (ch < 27) v = w_mask[((ch - 18) * 64 + cbase + c) * 9 + t];
            sw[i] = v;
        }
        __syncthreads();

        for (int c = 0; c < 32; c++) {
            const float* xc = sx + c * 324 + (typ << 1) * 18 + tx;
            float xv[4][3];
#pragma unroll
            for (int rr = 0; rr < 4; rr++)
#pragma unroll
                for (int dj = 0; dj < 3; dj++)
                    xv[rr][dj] = xc[rr * 18 + dj];
            const ulonglong2* wq = (const ulonglong2*)(sw + c * 252);
#pragma unroll
            for (int di = 0; di < 3; di++)
#pragma unroll
                for (int dj = 0; dj < 3; dj++) {
                    const int t = di * 3 + dj;
                    const unsigned long long x0 = pk2(xv[di][dj], xv[di][dj]);
                    const unsigned long long x1 = pk2(xv[di + 1][dj], xv[di + 1][dj]);
#pragma unroll
                    for (int q = 0; q < 7; q++) {
                        const ulonglong2 wv = wq[t * 7 + q];
                        acc0[2 * q]     = fma2(wv.x, x0, acc0[2 * q]);
                        acc0[2 * q + 1] = fma2(wv.y, x0, acc0[2 * q + 1]);
                        acc1[2 * q]     = fma2(wv.x, x1, acc1[2 * q]);
                        acc1[2 * q + 1] = fma2(wv.y, x1, acc1[2 * q + 1]);
                    }
                }
        }
        __syncthreads();
    }

    const int ow = tileX * 16 + tx;
#pragma unroll
    for (int px = 0; px < 2; px++) {
        const unsigned long long* acc = px ? acc1 : acc0;
        const int oh = tileY * 16 + (typ << 1) + px;
        const int hw = (oh << 7) + ow;
#pragma unroll
        for (int j = 0; j < 14; j++) {
            float lo, hi; upk2(acc[j], lo, hi);
            int ch = 2 * j;
            if (ch < 18) g_off[(b * 18 + ch) * HW + hw] = lo;
            else         g_mask[(b * 9 + ch - 18) * HW + hw] = 1.f / (1.f + expf(-lo));
            ch++;
            if (ch < 18)      g_off[(b * 18 + ch) * HW + hw] = hi;
            else if (ch < 27) g_mask[(b * 9 + ch - 18) * HW + hw] = 1.f / (1.f + expf(-hi));
        }
    }
}

// ---- k_dcn: mma.sync deformable conv ---------------------------------------
// grid: 1024 blocks (b*128 rows), 256 threads (8 warps x 16 pixels)
// dyn smem (1024-aligned): A_hi 16K | A_lo 16K | B_hi 8K | B_lo 8K
#define SMEM2 (49152 + 1024)

__global__ __launch_bounds__(256)
void k_dcn(const float* __restrict__ x,
           const float* __restrict__ b_dcn,
           float* __restrict__ out) {
    __shared__ float4 sW4[128];
    __shared__ int4   sO4[128];
    __shared__ float  sbias[64];
    extern __shared__ char dsm[];
    char* dgen = (char*)((((uintptr_t)dsm) + 1023) & ~(uintptr_t)1023);
    const unsigned aHi = smem_u32(dgen);
    const unsigned aLo = aHi + 16384;
    const unsigned bHi = aHi + 32768;
    const unsigned bLo = aHi + 40960;

    const int tid = threadIdx.x;
    const int wid = tid >> 5, lane = tid & 31;
    const int b = blockIdx.x >> 7;
    const int h = blockIdx.x & 127;
    const int hw0 = h << 7;
    const float* xb = x + (b << 20);

    if (tid < 64) sbias[tid] = b_dcn[tid];

    const int m0 = wid << 4;                 // warp's pixel base
    // A-frag ldmatrix lane mapping (x4: m16 x k16)
    const int as = lane >> 3;
    const int arow = m0 + (lane & 7) + ((as & 1) << 3);
    const int akc = as >> 1;
    // B-frag ldmatrix lane mapping (x2: n8 x k16), lanes 0..15 meaningful
    const int bl = lane & 15;
    const int brow = bl & 7;
    const int bkc = bl >> 3;

    float C[8][4];
#pragma unroll
    for (int n = 0; n < 8; n++)
#pragma unroll
        for (int i = 0; i < 4; i++) C[n][i] = 0.f;

    const int ps = tid & 127;     // pixel for sampling
    const int c0 = tid >> 7;      // channel half

#pragma unroll 1
    for (int k = 0; k < 9; k++) {
        // bilinear params: one pixel per thread (0..127)
        if (tid < 128) {
            const int p = tid;
            const float dy = g_off[(b * 18 + 2 * k) * HW + hw0 + p];
            const float dx = g_off[(b * 18 + 2 * k + 1) * HW + hw0 + p];
            const float m  = g_mask[(b * 9 + k) * HW + hw0 + p];
            const float py = (float)(h - 1 + k / 3) + dy;
            const float px = (float)(p - 1 + k % 3) + dx;
            const float y0f = floorf(py), x0f = floorf(px);
            const float wy1 = py - y0f, wx1 = px - x0f;
            const float wy0 = 1.f - wy1, wx0 = 1.f - wx1;
            const int y0 = (int)y0f, x0 = (int)x0f;
            const int y1 = y0 + 1,  x1 = x0 + 1;
            const float vy0 = ((unsigned)y0 < 128u) ? 1.f : 0.f;
            const float vy1 = ((unsigned)y1 < 128u) ? 1.f : 0.f;
            const float vx0 = ((unsigned)x0 < 128u) ? 1.f : 0.f;
            const float vx1 = ((unsigned)x1 < 128u) ? 1.f : 0.f;
            const int y0c = min(max(y0, 0), 127), y1c = min(max(y1, 0), 127);
            const int x0c = min(max(x0, 0), 127), x1c = min(max(x1, 0), 127);
            sW4[p] = make_float4(wy0 * wx0 * m * vy0 * vx0,
                                 wy0 * wx1 * m * vy0 * vx1,
                                 wy1 * wx0 * m * vy1 * vx0,
                                 wy1 * wx1 * m * vy1 * vx1);
            sO4[p] = make_int4((y0c << 7) + x0c, (y0c << 7) + x1c,
                               (y1c << 7) + x0c, (y1c << 7) + x1c);
        }
        // stage W hi/lo (pre-swizzled [o][c] tiles): 512 uint4 each
        {
            const uint4* sh = (const uint4*)(g_Bhi + (k << 11));
            const uint4* sl = (const uint4*)(g_Blo + (k << 11));
            uint4* dh = (uint4*)(dgen + 32768);
            uint4* dl = (uint4*)(dgen + 40960);
            dh[tid] = sh[tid]; dh[tid + 256] = sh[tid + 256];
            dl[tid] = sl[tid]; dl[tid + 256] = sl[tid + 256];
        }
        __syncthreads();

        // sample 32 channels/thread-half, write bf16x2 hi/lo swizzled [p][c]
        {
            const float4 Wp = sW4[ps];
            const int4   Op = sO4[ps];
            unsigned* Ah = (unsigned*)dgen;
            unsigned* Al = (unsigned*)(dgen + 16384);
#pragma unroll 4
            for (int i = 0; i < 16; i++) {
                const int c = (c0 << 5) + 2 * i;
                const float* p0 = xb + (c << 14);
                const float* p1 = p0 + 16384;
                const float s0 = Wp.x * p0[Op.x] + Wp.y * p0[Op.y]
                               + Wp.z * p0[Op.z] + Wp.w * p0[Op.w];
                const float s1 = Wp.x * p1[Op.x] + Wp.y * p1[Op.y]
                               + Wp.z * p1[Op.z] + Wp.w * p1[Op.w];
                const __nv_bfloat16 h0b = __float2bfloat16(s0);
                const __nv_bfloat16 h1b = __float2bfloat16(s1);
                const __nv_bfloat16 l0b = __float2bfloat16(s0 - __bfloat162float(h0b));
                const __nv_bfloat16 l1b = __float2bfloat16(s1 - __bfloat162float(h1b));
                const int idx = swz((ps << 7) + (c << 1)) >> 2;
                Ah[idx] = ((unsigned)__bfloat16_as_ushort(h1b) << 16)
                        | __bfloat16_as_ushort(h0b);
                Al[idx] = ((unsigned)__bfloat16_as_ushort(l1b) << 16)
                        | __bfloat16_as_ushort(l0b);
            }
        }
        __syncthreads();

        // GEMM: C[16p x 64o] += S[16p x 64c] * W[64o x 64c]^T  (hi/lo split)
        {
            unsigned Ahf[4][4], Alf[4][4];
#pragma unroll
            for (int ks = 0; ks < 4; ks++) {
                const unsigned ad = swz(arow * 128 + (ks * 2 + akc) * 16);
                ldx4(Ahf[ks], aHi + ad);
                ldx4(Alf[ks], aLo + ad);
            }
#pragma unroll
            for (int n = 0; n < 8; n++) {
#pragma unroll
                for (int ks = 0; ks < 4; ks++) {
                    const unsigned bd =
                        swz((n * 8 + brow) * 128 + (ks * 2 + bkc) * 16);
                    unsigned bh0, bh1, bl0, bl1;
                    ldx2(bh0, bh1, bHi + bd);
                    ldx2(bl0, bl1, bLo + bd);
                    mma_bf16(C[n], Ahf[ks], bh0, bh1);
                    mma_bf16(C[n], Ahf[ks], bl0, bl1);
                    mma_bf16(C[n], Alf[ks], bh0, bh1);
                }
            }
        }
        __syncthreads();
    }

    // epilogue: C frag (m16n8): c0,c1 -> row=lane>>2, col=2*(lane&3); c2,c3 row+8
    float* ob = out + (b << 20) + hw0;
    const int prow = m0 + (lane >> 2);
    const int ocol = 2 * (lane & 3);
#pragma unroll
    for (int n = 0; n < 8; n++) {
        const int o = n * 8 + ocol;
        ob[(o << 14) + prow]           = C[n][0] + sbias[o];
        ob[((o + 1) << 14) + prow]     = C[n][1] + sbias[o + 1];
        ob[(o << 14) + prow + 8]       = C[n][2] + sbias[o];
        ob[((o + 1) << 14) + prow + 8] = C[n][3] + sbias[o + 1];
    }
}

// ---------------------------------------------------------------------------
extern "C" void kernel_launch(void* const* d_in, const int* in_sizes, int n_in,
                              void* d_out, int out_size) {
    const float* x      = (const float*)d_in[0];
    const float* w_off  = (const float*)d_in[1];
    const float* b_off  = (const float*)d_in[2];
    const float* w_mask = (const float*)d_in[3];
    const float* b_mask = (const float*)d_in[4];
    const float* w_dcn  = (const float*)d_in[5];
    const float* b_dcn  = (const float*)d_in[6];
    float* out = (float*)d_out;

    cudaFuncSetAttribute(k_offmask, cudaFuncAttributeMaxDynamicSharedMemorySize, SMEM1);
    cudaFuncSetAttribute(k_dcn,     cudaFuncAttributeMaxDynamicSharedMemorySize, SMEM2);

    k_offmask<<<Bb * 64, 128, SMEM1>>>(x, w_off, b_off, w_mask, b_mask, w_dcn);
    k_dcn<<<Bb * 128, 256, SMEM2>>>(x, b_dcn, out);
}

// round 13
// speedup vs baseline: 2.3643x; 1.5251x over previous
#include <cuda_runtime.h>
#include <cuda_bf16.h>
#include <math.h>
#include <stdint.h>

// ---------------------------------------------------------------------------
// DCNv2: B=8, C=64, H=W=128, K=3, O=64  — all-HMMA version
//  k_prep:    bf16 hi/lo split + SW128 byte-swizzle of w_dcn and w_off/w_mask
//  k_offmask: 27-ch 3x3 conv as 9 shift-GEMMs on mma.sync (bf16 hi/lo, fp32 acc)
//  k_dcn:     per-row deformable GEMM on mma.sync; STS.128 conflict-free
//             staging of sampled A; 32p x 32o warp tiles.
// ---------------------------------------------------------------------------

#define Bb 8
#define HW (128*128)

__device__ float g_off [Bb * 18 * HW];
__device__ float g_mask[Bb * 9  * HW];
__device__ __align__(16) unsigned g_Bhi[9 * 2048];  // dcn W  [k][swz(o*128+c*2)>>2]
__device__ __align__(16) unsigned g_Blo[9 * 2048];
__device__ __align__(16) unsigned g_Whi[9 * 1024];  // off/mask W (32o x 64c per tap)
__device__ __align__(16) unsigned g_Wlo[9 * 1024];

// ---- helpers ---------------------------------------------------------------
__device__ __forceinline__ unsigned smem_u32(const void* p) {
    unsigned a;
    asm("{ .reg .u64 t; cvta.to.shared.u64 t, %1; cvt.u32.u64 %0, t; }"
        : "=r"(a) : "l"(p));
    return a;
}
__device__ __forceinline__ void ldx4(unsigned* r, unsigned addr) {
    asm volatile("ldmatrix.sync.aligned.m8n8.x4.shared.b16 {%0,%1,%2,%3}, [%4];"
                 : "=r"(r[0]), "=r"(r[1]), "=r"(r[2]), "=r"(r[3]) : "r"(addr));
}
__device__ __forceinline__ void ldx2(unsigned& r0, unsigned& r1, unsigned addr) {
    asm volatile("ldmatrix.sync.aligned.m8n8.x2.shared.b16 {%0,%1}, [%2];"
                 : "=r"(r0), "=r"(r1) : "r"(addr));
}
__device__ __forceinline__ void mma_bf16(float* c, const unsigned* a,
                                         unsigned b0, unsigned b1) {
    asm volatile("mma.sync.aligned.m16n8k16.row.col.f32.bf16.bf16.f32 "
                 "{%0,%1,%2,%3}, {%4,%5,%6,%7}, {%8,%9}, {%0,%1,%2,%3};"
                 : "+f"(c[0]), "+f"(c[1]), "+f"(c[2]), "+f"(c[3])
                 : "r"(a[0]), "r"(a[1]), "r"(a[2]), "r"(a[3]), "r"(b0), "r"(b1));
}
__device__ __forceinline__ int swz(int off) { return off ^ ((off >> 3) & 0x70); }
__device__ __forceinline__ void split2(float s0, float s1, unsigned& hi, unsigned& lo) {
    __nv_bfloat16 h0 = __float2bfloat16(s0), h1 = __float2bfloat16(s1);
    __nv_bfloat16 l0 = __float2bfloat16(s0 - __bfloat162float(h0));
    __nv_bfloat16 l1 = __float2bfloat16(s1 - __bfloat162float(h1));
    hi = ((unsigned)__bfloat16_as_ushort(h1) << 16) | __bfloat16_as_ushort(h0);
    lo = ((unsigned)__bfloat16_as_ushort(l1) << 16) | __bfloat16_as_ushort(l0);
}

// ---- k_prep: weight split + swizzle ----------------------------------------
__global__ void k_prep(const float* __restrict__ w_dcn,
                       const float* __restrict__ w_off,
                       const float* __restrict__ w_mask) {
    int gi = blockIdx.x * 256 + threadIdx.x;
    if (gi < 9 * 2048) {                      // dcn: 9 taps x 64o x 32 c-pairs
        int k = gi >> 11;
        int rem = gi & 2047;
        int o = rem >> 5, c = (rem & 31) << 1;
        unsigned hi, lo;
        split2(w_dcn[((o << 6) + c) * 9 + k],
               w_dcn[((o << 6) + c + 1) * 9 + k], hi, lo);
        int idx = swz((o << 7) + (c << 1)) >> 2;
        g_Bhi[(k << 11) + idx] = hi;
        g_Blo[(k << 11) + idx] = lo;
    } else if (gi < 9 * 2048 + 9 * 1024) {    // off/mask: 9 taps x 32o x 32 c-pairs
        int gj = gi - 9 * 2048;
        int k = gj >> 10;
        int rem = gj & 1023;
        int o = rem >> 5, c = (rem & 31) << 1;
        float v0 = 0.f, v1 = 0.f;
        if (o < 18)      { v0 = w_off [(o * 64 + c) * 9 + k];
                           v1 = w_off [(o * 64 + c + 1) * 9 + k]; }
        else if (o < 27) { v0 = w_mask[((o - 18) * 64 + c) * 9 + k];
                           v1 = w_mask[((o - 18) * 64 + c + 1) * 9 + k]; }
        unsigned hi, lo;
        split2(v0, v1, hi, lo);
        int idx = swz((o << 7) + (c << 1)) >> 2;
        g_Whi[(k << 10) + idx] = hi;
        g_Wlo[(k << 10) + idx] = lo;
    }
}

// ---- k_offmask: 3x3 conv as 9 shift-GEMMs ----------------------------------
// grid: 1024 blocks (b*128 rows), 256 threads (8 warps: 4 in p x 2 in o)
// smem: 6 x-tiles [130][64c] bf16 (hi 0..2, lo 3..5) + B buf 8KB
#define OM_TILE 16640
#define OM_B    (6 * OM_TILE)          // 99840
#define SMEM_OM (OM_B + 8192 + 1024)

__global__ __launch_bounds__(256)
void k_offmask(const float* __restrict__ x,
               const float* __restrict__ b_off,
               const float* __restrict__ b_mask) {
    __shared__ float sbias[32];
    extern __shared__ char dsm0[];
    char* base = (char*)((((uintptr_t)dsm0) + 1023) & ~(uintptr_t)1023);
    const unsigned u_base = smem_u32(base);
    const unsigned u_B = u_base + OM_B;

    const int tid = threadIdx.x;
    const int lane = tid & 31, wid = tid >> 5;
    const int b = blockIdx.x >> 7;
    const int h = blockIdx.x & 127;
    const int hw0 = h << 7;
    const float* xb = x + (b << 20);

    if (tid < 32)
        sbias[tid] = (tid < 18) ? b_off[tid] : ((tid < 27) ? b_mask[tid - 18] : 0.f);

    // zero edge rows (w' = -1 and 128): 12 tile-rows x 8 uint4
    if (tid < 96) {
        int r = tid >> 3;                 // 0..11
        int ts = r >> 1;                  // 0..5 (tile index)
        int row = (r & 1) ? 129 : 0;
        int addr = ts * OM_TILE + swz(row * 128 + ((tid & 7) << 4));
        *(uint4*)(base + addr) = make_uint4(0, 0, 0, 0);
    }

    // stage x rows h-1..h+1 transposed: tile[di] row (w+1), col c; bf16 hi/lo
#pragma unroll 1
    for (int it = 0; it < 12; it++) {
        int T = wid + (it << 3);          // 0..95
        int di = T >> 5;
        int rem = T & 31;
        int cg = rem >> 2, wq = rem & 3;  // 8-channel group, w-quarter
        int w = (wq << 5) + lane;
        int gy = h - 1 + di;
        float v[8];
        if ((unsigned)gy < 128u) {
            const float* xp = xb + ((cg * 8) << 14) + (gy << 7) + w;
#pragma unroll
            for (int j = 0; j < 8; j++) v[j] = xp[j << 14];
        } else {
#pragma unroll
            for (int j = 0; j < 8; j++) v[j] = 0.f;
        }
        unsigned wh[4], wl[4];
#pragma unroll
        for (int u = 0; u < 4; u++) split2(v[2 * u], v[2 * u + 1], wh[u], wl[u]);
        int addr = swz((w + 1) * 128 + (cg << 4));
        *(uint4*)(base + di * OM_TILE + addr) = make_uint4(wh[0], wh[1], wh[2], wh[3]);
        *(uint4*)(base + (3 + di) * OM_TILE + addr) = make_uint4(wl[0], wl[1], wl[2], wl[3]);
    }
    __syncthreads();

    // warp tiles: 32p x 16o
    const int wp = wid >> 1, wo = wid & 1;
    const int m0 = wp << 5, o0 = wo << 4;
    const int as = lane >> 3;
    const int arl = (lane & 7) + ((as & 1) << 3);
    const int akc = as >> 1;
    const int bl = lane & 15, brow = bl & 7, bkc = bl >> 3;

    float C[2][2][4];
#pragma unroll
    for (int i = 0; i < 2; i++)
#pragma unroll
        for (int j = 0; j < 2; j++)
#pragma unroll
            for (int q = 0; q < 4; q++) C[i][j][q] = 0.f;

#pragma unroll 1
    for (int t = 0; t < 9; t++) {
        const int di = t / 3, dj = t - 3 * di;
        // stage B_t (4KB hi + 4KB lo)
        {
            const uint4* sh = (const uint4*)(g_Whi + (t << 10));
            const uint4* sl = (const uint4*)(g_Wlo + (t << 10));
            ((uint4*)(base + OM_B))[tid] = sh[tid];
            ((uint4*)(base + OM_B + 4096))[tid] = sl[tid];
        }
        __syncthreads();

        const unsigned tHi = u_base + di * OM_TILE;
        const unsigned tLo = u_base + (3 + di) * OM_TILE;
#pragma unroll
        for (int ks = 0; ks < 4; ks++) {
            unsigned bh[2][2], bv[2][2];
#pragma unroll
            for (int nt = 0; nt < 2; nt++) {
                const unsigned ad = swz((o0 + nt * 8 + brow) * 128 + (ks * 2 + bkc) * 16);
                ldx2(bh[nt][0], bh[nt][1], u_B + ad);
                ldx2(bv[nt][0], bv[nt][1], u_B + 4096 + ad);
            }
#pragma unroll
            for (int mt = 0; mt < 2; mt++) {
                unsigned Af[4], Alf[4];
                const unsigned ad =
                    swz((m0 + mt * 16 + arl + dj) * 128 + (ks * 2 + akc) * 16);
                ldx4(Af, tHi + ad);
                ldx4(Alf, tLo + ad);
#pragma unroll
                for (int nt = 0; nt < 2; nt++) {
                    mma_bf16(C[mt][nt], Af, bh[nt][0], bh[nt][1]);
                    mma_bf16(C[mt][nt], Af, bv[nt][0], bv[nt][1]);
                    mma_bf16(C[mt][nt], Alf, bh[nt][0], bh[nt][1]);
                }
            }
        }
        __syncthreads();
    }

    // epilogue -> g_off / g_mask
    const int prow = lane >> 2;
    const int oc = 2 * (lane & 3);
#pragma unroll
    for (int mt = 0; mt < 2; mt++)
#pragma unroll
        for (int nt = 0; nt < 2; nt++)
#pragma unroll
            for (int q = 0; q < 4; q++) {
                const int p = m0 + mt * 16 + prow + ((q >> 1) << 3);
                const int ch = o0 + nt * 8 + oc + (q & 1);
                const float v = C[mt][nt][q] + sbias[ch];
                if (ch < 18)
                    g_off[(b * 18 + ch) * HW + hw0 + p] = v;
                else if (ch < 27)
                    g_mask[(b * 9 + ch - 18) * HW + hw0 + p] = 1.f / (1.f + expf(-v));
            }
}

// ---- k_dcn: deformable GEMM ------------------------------------------------
// grid: 1024 blocks (b*128 rows), 256 threads (8 warps: 4 in p x 2 in o)
// dyn smem: A_hi 16K | A_lo 16K | B_hi 8K | B_lo 8K
#define SMEM2 (49152 + 1024)

__global__ __launch_bounds__(256)
void k_dcn(const float* __restrict__ x,
           const float* __restrict__ b_dcn,
           float* __restrict__ out) {
    __shared__ float4 sW4[128];
    __shared__ int4   sO4[128];
    __shared__ float  sbias[64];
    extern __shared__ char dsm[];
    char* dgen = (char*)((((uintptr_t)dsm) + 1023) & ~(uintptr_t)1023);
    const unsigned aHi = smem_u32(dgen);
    const unsigned aLo = aHi + 16384;
    const unsigned bHi = aHi + 32768;
    const unsigned bLo = aHi + 40960;

    const int tid = threadIdx.x;
    const int wid = tid >> 5, lane = tid & 31;
    const int b = blockIdx.x >> 7;
    const int h = blockIdx.x & 127;
    const int hw0 = h << 7;
    const float* xb = x + (b << 20);

    if (tid < 64) sbias[tid] = b_dcn[tid];

    // warp tiles: 32p x 32o
    const int wp = wid >> 1, wo = wid & 1;
    const int m0 = wp << 5, o0 = wo << 5;
    const int as = lane >> 3;
    const int arl = (lane & 7) + ((as & 1) << 3);
    const int akc = as >> 1;
    const int bl = lane & 15, brow = bl & 7, bkc = bl >> 3;

    float C[2][4][4];
#pragma unroll
    for (int i = 0; i < 2; i++)
#pragma unroll
        for (int j = 0; j < 4; j++)
#pragma unroll
            for (int q = 0; q < 4; q++) C[i][j][q] = 0.f;

    const int ps = tid & 127;     // sampling pixel
    const int c0 = tid >> 7;      // channel half

#pragma unroll 1
    for (int k = 0; k < 9; k++) {
        // bilinear params: one pixel per thread (0..127)
        if (tid < 128) {
            const int p = tid;
            const float dy = g_off[(b * 18 + 2 * k) * HW + hw0 + p];
            const float dx = g_off[(b * 18 + 2 * k + 1) * HW + hw0 + p];
            const float m  = g_mask[(b * 9 + k) * HW + hw0 + p];
            const float py = (float)(h - 1 + k / 3) + dy;
            const float px = (float)(p - 1 + k % 3) + dx;
            const float y0f = floorf(py), x0f = floorf(px);
            const float wy1 = py - y0f, wx1 = px - x0f;
            const float wy0 = 1.f - wy1, wx0 = 1.f - wx1;
            const int y0 = (int)y0f, x0 = (int)x0f;
            const int y1 = y0 + 1,  x1 = x0 + 1;
            const float vy0 = ((unsigned)y0 < 128u) ? 1.f : 0.f;
            const float vy1 = ((unsigned)y1 < 128u) ? 1.f : 0.f;
            const float vx0 = ((unsigned)x0 < 128u) ? 1.f : 0.f;
            const float vx1 = ((unsigned)x1 < 128u) ? 1.f : 0.f;
            const int y0c = min(max(y0, 0), 127), y1c = min(max(y1, 0), 127);
            const int x0c = min(max(x0, 0), 127), x1c = min(max(x1, 0), 127);
            sW4[p] = make_float4(wy0 * wx0 * m * vy0 * vx0,
                                 wy0 * wx1 * m * vy0 * vx1,
                                 wy1 * wx0 * m * vy1 * vx0,
                                 wy1 * wx1 * m * vy1 * vx1);
            sO4[p] = make_int4((y0c << 7) + x0c, (y0c << 7) + x1c,
                               (y1c << 7) + x0c, (y1c << 7) + x1c);
        }
        // stage W hi/lo (pre-swizzled [o][c] tiles)
        {
            const uint4* sh = (const uint4*)(g_Bhi + (k << 11));
            const uint4* sl = (const uint4*)(g_Blo + (k << 11));
            uint4* dh = (uint4*)(dgen + 32768);
            uint4* dl = (uint4*)(dgen + 40960);
            dh[tid] = sh[tid]; dh[tid + 256] = sh[tid + 256];
            dl[tid] = sl[tid]; dl[tid + 256] = sl[tid + 256];
        }
        __syncthreads();

        // sample 32 channels per thread; STS.128 conflict-free staging
        {
            const float4 Wp = sW4[ps];
            const int4   Op = sO4[ps];
#pragma unroll
            for (int g = 0; g < 4; g++) {
                unsigned wh[4], wl[4];
#pragma unroll
                for (int u = 0; u < 4; u++) {
                    const int c = (c0 << 5) + (g << 3) + (u << 1);
                    const float* p0 = xb + (c << 14);
                    const float* p1 = p0 + 16384;
                    const float s0 = Wp.x * p0[Op.x] + Wp.y * p0[Op.y]
                                   + Wp.z * p0[Op.z] + Wp.w * p0[Op.w];
                    const float s1 = Wp.x * p1[Op.x] + Wp.y * p1[Op.y]
                                   + Wp.z * p1[Op.z] + Wp.w * p1[Op.w];
                    split2(s0, s1, wh[u], wl[u]);
                }
                const int addr = swz((ps << 7) + (c0 << 6) + (g << 4));
                *(uint4*)(dgen + addr) = make_uint4(wh[0], wh[1], wh[2], wh[3]);
                *(uint4*)(dgen + 16384 + addr) = make_uint4(wl[0], wl[1], wl[2], wl[3]);
            }
        }
        __syncthreads();

        // GEMM: C[32p x 32o] += S[32p x 64c] * W[32o x 64c]^T (hi/lo split)
#pragma unroll
        for (int ks = 0; ks < 4; ks++) {
            unsigned bh[4][2], bv[4][2];
#pragma unroll
            for (int nt = 0; nt < 4; nt++) {
                const unsigned ad = swz((o0 + nt * 8 + brow) * 128 + (ks * 2 + bkc) * 16);
                ldx2(bh[nt][0], bh[nt][1], bHi + ad);
                ldx2(bv[nt][0], bv[nt][1], bLo + ad);
            }
#pragma unroll
            for (int mt = 0; mt < 2; mt++) {
                unsigned Af[4], Alf[4];
                const unsigned ad =
                    swz((m0 + mt * 16 + arl) * 128 + (ks * 2 + akc) * 16);
                ldx4(Af, aHi + ad);
                ldx4(Alf, aLo + ad);
#pragma unroll
                for (int nt = 0; nt < 4; nt++) {
                    mma_bf16(C[mt][nt], Af, bh[nt][0], bh[nt][1]);
                    mma_bf16(C[mt][nt], Af, bv[nt][0], bv[nt][1]);
                    mma_bf16(C[mt][nt], Alf, bh[nt][0], bh[nt][1]);
                }
            }
        }
        __syncthreads();
    }

    // epilogue
    float* ob = out + (b << 20) + hw0;
    const int prow = lane >> 2;
    const int oc = 2 * (lane & 3);
#pragma unroll
    for (int mt = 0; mt < 2; mt++)
#pragma unroll
        for (int nt = 0; nt < 4; nt++)
#pragma unroll
            for (int q = 0; q < 4; q++) {
                const int p = m0 + mt * 16 + prow + ((q >> 1) << 3);
                const int o = o0 + nt * 8 + oc + (q & 1);
                ob[(o << 14) + p] = C[mt][nt][q] + sbias[o];
            }
}

// ---------------------------------------------------------------------------
extern "C" void kernel_launch(void* const* d_in, const int* in_sizes, int n_in,
                              void* d_out, int out_size) {
    const float* x      = (const float*)d_in[0];
    const float* w_off  = (const float*)d_in[1];
    const float* b_off  = (const float*)d_in[2];
    const float* w_mask = (const float*)d_in[3];
    const float* b_mask = (const float*)d_in[4];
    const float* w_dcn  = (const float*)d_in[5];
    const float* b_dcn  = (const float*)d_in[6];
    float* out = (float*)d_out;

    cudaFuncSetAttribute(k_offmask, cudaFuncAttributeMaxDynamicSharedMemorySize, SMEM_OM);
    cudaFuncSetAttribute(k_dcn,     cudaFuncAttributeMaxDynamicSharedMemorySize, SMEM2);

    k_prep<<<(9 * 2048 + 9 * 1024 + 255) / 256, 256>>>(w_dcn, w_off, w_mask);
    k_offmask<<<Bb * 128, 256, SMEM_OM>>>(x, b_off, b_mask);
    k_dcn<<<Bb * 128, 256, SMEM2>>>(x, b_dcn, out);
}

// round 14
// speedup vs baseline: 2.9053x; 1.2288x over previous
#include <cuda_runtime.h>
#include <cuda_bf16.h>
#include <math.h>
#include <stdint.h>

// ---------------------------------------------------------------------------
// DCNv2: B=8, C=64, H=W=128, K=3, O=64  — all-HMMA, fragment-direct B version
//  k_prep:    bf16 hi/lo split of w_dcn / w_off / w_mask directly into
//             m16n8k16 B-fragment register order (uint4 = {b0h,b1h,b0l,b1l})
//  k_offmask: 27-ch 3x3 conv as 9 shift-GEMMs; A tiles staged once,
//             tap loop syncless (B frags via coalesced LDG).
//  k_dcn:     per-row deformable GEMM; ping-pong A buffers, ONE sync per tap;
//             B frags via LDG; coalesced epilogue via padded smem transpose.
// ---------------------------------------------------------------------------

#define Bb 8
#define HW (128*128)

__device__ float g_off [Bb * 18 * HW];
__device__ float g_mask[Bb * 9  * HW];
__device__ __align__(16) uint4 g_Bfrag[9 * 1024];   // dcn: [k][wo2][ks4][nt4][lane32]
__device__ __align__(16) uint4 g_Wfrag[9 * 512];    // off/mask: [k][wo2][ks4][nt2][lane32]

// ---- helpers ---------------------------------------------------------------
__device__ __forceinline__ unsigned smem_u32(const void* p) {
    unsigned a;
    asm("{ .reg .u64 t; cvta.to.shared.u64 t, %1; cvt.u32.u64 %0, t; }"
        : "=r"(a) : "l"(p));
    return a;
}
__device__ __forceinline__ void ldx4(unsigned* r, unsigned addr) {
    asm volatile("ldmatrix.sync.aligned.m8n8.x4.shared.b16 {%0,%1,%2,%3}, [%4];"
                 : "=r"(r[0]), "=r"(r[1]), "=r"(r[2]), "=r"(r[3]) : "r"(addr));
}
__device__ __forceinline__ void mma_bf16(float* c, const unsigned* a,
                                         unsigned b0, unsigned b1) {
    asm volatile("mma.sync.aligned.m16n8k16.row.col.f32.bf16.bf16.f32 "
                 "{%0,%1,%2,%3}, {%4,%5,%6,%7}, {%8,%9}, {%0,%1,%2,%3};"
                 : "+f"(c[0]), "+f"(c[1]), "+f"(c[2]), "+f"(c[3])
                 : "r"(a[0]), "r"(a[1]), "r"(a[2]), "r"(a[3]), "r"(b0), "r"(b1));
}
__device__ __forceinline__ int swz(int off) { return off ^ ((off >> 3) & 0x70); }
__device__ __forceinline__ void split2(float s0, float s1, unsigned& hi, unsigned& lo) {
    __nv_bfloat16 h0 = __float2bfloat16(s0), h1 = __float2bfloat16(s1);
    __nv_bfloat16 l0 = __float2bfloat16(s0 - __bfloat162float(h0));
    __nv_bfloat16 l1 = __float2bfloat16(s1 - __bfloat162float(h1));
    hi = ((unsigned)__bfloat16_as_ushort(h1) << 16) | __bfloat16_as_ushort(h0);
    lo = ((unsigned)__bfloat16_as_ushort(l1) << 16) | __bfloat16_as_ushort(l0);
}

// ---- k_prep: weights -> MMA B-fragment order -------------------------------
// m16n8k16 B frag: b0 = {B[k=2(lane%4)][n=lane/4], B[k+1][n]}, b1 = k+8,k+9
__global__ void k_prep(const float* __restrict__ w_dcn,
                       const float* __restrict__ w_off,
                       const float* __restrict__ w_mask) {
    int gi = blockIdx.x * 256 + threadIdx.x;
    if (gi < 9 * 1024) {             // dcn: nt bits5-6, ks bits7-8, wo bit9, tap>>10
        int lane = gi & 31;
        int nt = (gi >> 5) & 3, ks = (gi >> 7) & 3, wo = (gi >> 9) & 1, tap = gi >> 10;
        int o = wo * 32 + nt * 8 + (lane >> 2);
        int c = ks * 16 + 2 * (lane & 3);
        unsigned h0, l0, h1, l1;
        split2(w_dcn[((o << 6) + c) * 9 + tap],
               w_dcn[((o << 6) + c + 1) * 9 + tap], h0, l0);
        split2(w_dcn[((o << 6) + c + 8) * 9 + tap],
               w_dcn[((o << 6) + c + 9) * 9 + tap], h1, l1);
        g_Bfrag[gi] = make_uint4(h0, h1, l0, l1);
    } else if (gi < 9 * 1024 + 9 * 512) {  // off/mask: nt bit5, ks bits6-7, wo bit8
        int gj = gi - 9 * 1024;
        int lane = gj & 31;
        int nt = (gj >> 5) & 1, ks = (gj >> 6) & 3, wo = (gj >> 8) & 1, tap = gj >> 9;
        int o = wo * 16 + nt * 8 + (lane >> 2);
        int c = ks * 16 + 2 * (lane & 3);
        float v[4];
#pragma unroll
        for (int u = 0; u < 4; u++) {
            int cc = c + (u >> 1) * 8 + (u & 1);
            v[u] = (o < 18) ? w_off[(o * 64 + cc) * 9 + tap]
                 : (o < 27) ? w_mask[((o - 18) * 64 + cc) * 9 + tap] : 0.f;
        }
        unsigned h0, l0, h1, l1;
        split2(v[0], v[1], h0, l0);
        split2(v[2], v[3], h1, l1);
        g_Wfrag[gj] = make_uint4(h0, h1, l0, l1);
    }
}

// ---- k_offmask: 3x3 conv as 9 syncless shift-GEMMs -------------------------
// grid: 1024 blocks (b*128 rows), 256 threads (8 warps: 4 in p x 2 in o)
// smem: 6 x-tiles [130 rows][64c] bf16 (hi 0..2, lo 3..5); S reuses tile 0
#define OM_TILE 16640
#define SMEM_OM (6 * OM_TILE + 1024)

__global__ __launch_bounds__(256)
void k_offmask(const float* __restrict__ x,
               const float* __restrict__ b_off,
               const float* __restrict__ b_mask) {
    __shared__ float sbias[32];
    extern __shared__ char dsm0[];
    char* base = (char*)((((uintptr_t)dsm0) + 1023) & ~(uintptr_t)1023);
    const unsigned u_base = smem_u32(base);

    const int tid = threadIdx.x;
    const int lane = tid & 31, wid = tid >> 5;
    const int b = blockIdx.x >> 7;
    const int h = blockIdx.x & 127;
    const int hw0 = h << 7;
    const float* xb = x + (b << 20);

    if (tid < 32)
        sbias[tid] = (tid < 18) ? b_off[tid] : ((tid < 27) ? b_mask[tid - 18] : 0.f);

    // zero edge rows (w' = -1 and 128)
    if (tid < 96) {
        int r = tid >> 3;
        int ts = r >> 1;
        int row = (r & 1) ? 129 : 0;
        int addr = ts * OM_TILE + swz(row * 128 + ((tid & 7) << 4));
        *(uint4*)(base + addr) = make_uint4(0, 0, 0, 0);
    }
    // stage x rows h-1..h+1 transposed: tile[di] row (w+1), col c; hi/lo
#pragma unroll 1
    for (int it = 0; it < 12; it++) {
        int T = wid + (it << 3);
        int di = T >> 5;
        int rem = T & 31;
        int cg = rem >> 2, wq = rem & 3;
        int w = (wq << 5) + lane;
        int gy = h - 1 + di;
        float v[8];
        if ((unsigned)gy < 128u) {
            const float* xp = xb + ((cg * 8) << 14) + (gy << 7) + w;
#pragma unroll
            for (int j = 0; j < 8; j++) v[j] = xp[j << 14];
        } else {
#pragma unroll
            for (int j = 0; j < 8; j++) v[j] = 0.f;
        }
        unsigned wh[4], wl[4];
#pragma unroll
        for (int u = 0; u < 4; u++) split2(v[2 * u], v[2 * u + 1], wh[u], wl[u]);
        int addr = swz((w + 1) * 128 + (cg << 4));
        *(uint4*)(base + di * OM_TILE + addr) = make_uint4(wh[0], wh[1], wh[2], wh[3]);
        *(uint4*)(base + (3 + di) * OM_TILE + addr) = make_uint4(wl[0], wl[1], wl[2], wl[3]);
    }
    __syncthreads();

    // warp tiles: 32p x 16o
    const int wp = wid >> 1, wo = wid & 1;
    const int m0 = wp << 5, o0 = wo << 4;
    const int as = lane >> 3;
    const int arl = (lane & 7) + ((as & 1) << 3);
    const int akc = as >> 1;

    float C[2][2][4];
#pragma unroll
    for (int i = 0; i < 2; i++)
#pragma unroll
        for (int j = 0; j < 2; j++)
#pragma unroll
            for (int q = 0; q < 4; q++) C[i][j][q] = 0.f;

#pragma unroll 1
    for (int t = 0; t < 9; t++) {
        const int di = t / 3, dj = t - 3 * di;
        const unsigned tHi = u_base + di * OM_TILE;
        const unsigned tLo = u_base + (3 + di) * OM_TILE;
        const uint4* bk = g_Wfrag + ((t * 2 + wo) << 8) + lane;
#pragma unroll
        for (int ks = 0; ks < 4; ks++) {
            uint4 bf[2];
#pragma unroll
            for (int nt = 0; nt < 2; nt++) bf[nt] = bk[(ks * 2 + nt) << 5];
#pragma unroll
            for (int mt = 0; mt < 2; mt++) {
                unsigned Af[4], Alf[4];
                const unsigned ad =
                    swz((m0 + mt * 16 + arl + dj) * 128 + (ks * 2 + akc) * 16);
                ldx4(Af, tHi + ad);
                ldx4(Alf, tLo + ad);
#pragma unroll
                for (int nt = 0; nt < 2; nt++) {
                    mma_bf16(C[mt][nt], Af, bf[nt].x, bf[nt].y);
                    mma_bf16(C[mt][nt], Af, bf[nt].z, bf[nt].w);
                    mma_bf16(C[mt][nt], Alf, bf[nt].x, bf[nt].y);
                }
            }
        }
    }
    __syncthreads();

    // transpose to S[32ch][132] then coalesced stores (+bias, sigmoid on mask)
    float* S = (float*)base;
    const int prow = lane >> 2;
    const int oc = 2 * (lane & 3);
#pragma unroll
    for (int mt = 0; mt < 2; mt++)
#pragma unroll
        for (int nt = 0; nt < 2; nt++)
#pragma unroll
            for (int q = 0; q < 4; q++) {
                const int p = m0 + mt * 16 + prow + ((q >> 1) << 3);
                const int ch = o0 + nt * 8 + oc + (q & 1);
                S[ch * 132 + p] = C[mt][nt][q] + sbias[ch];
            }
    __syncthreads();
#pragma unroll
    for (int j = 0; j < 4; j++) {
        const int idx = j * 256 + tid;
        if (idx < 27 * 32) {
            const int ch = idx >> 5, p4 = idx & 31;
            float4 v = *(float4*)(S + ch * 132 + p4 * 4);
            if (ch < 18) {
                *(float4*)(g_off + (b * 18 + ch) * HW + hw0 + p4 * 4) = v;
            } else {
                v.x = 1.f / (1.f + expf(-v.x));
                v.y = 1.f / (1.f + expf(-v.y));
                v.z = 1.f / (1.f + expf(-v.z));
                v.w = 1.f / (1.f + expf(-v.w));
                *(float4*)(g_mask + (b * 9 + ch - 18) * HW + hw0 + p4 * 4) = v;
            }
        }
    }
}

// ---- k_dcn: deformable GEMM, ping-pong A, one sync per tap -----------------
// grid: 1024 blocks (b*128 rows), 256 threads (8 warps: 4 in p x 2 in o)
// dyn smem: A buf0 32K | A buf1 32K  (hi 16K + lo 16K each); S reuses buf0+
#define SMEM2 (65536 + 1024)

__global__ __launch_bounds__(256, 2)
void k_dcn(const float* __restrict__ x,
           const float* __restrict__ b_dcn,
           float* __restrict__ out) {
    __shared__ float sbias[64];
    extern __shared__ char dsm[];
    char* dgen = (char*)((((uintptr_t)dsm) + 1023) & ~(uintptr_t)1023);
    const unsigned uA = smem_u32(dgen);

    const int tid = threadIdx.x;
    const int wid = tid >> 5, lane = tid & 31;
    const int b = blockIdx.x >> 7;
    const int h = blockIdx.x & 127;
    const int hw0 = h << 7;
    const float* xb = x + (b << 20);

    if (tid < 64) sbias[tid] = b_dcn[tid];

    // warp tiles: 32p x 32o
    const int wp = wid >> 1, wo = wid & 1;
    const int m0 = wp << 5, o0 = wo << 5;
    const int as = lane >> 3;
    const int arl = (lane & 7) + ((as & 1) << 3);
    const int akc = as >> 1;

    float C[2][4][4];
#pragma unroll
    for (int i = 0; i < 2; i++)
#pragma unroll
        for (int j = 0; j < 4; j++)
#pragma unroll
            for (int q = 0; q < 4; q++) C[i][j][q] = 0.f;

    const int ps = tid & 127;     // sampling pixel (dup across halves)
    const int c0 = tid >> 7;      // channel half

#pragma unroll 1
    for (int k = 0; k < 9; k++) {
        // bilinear params: computed locally (no smem, no extra sync)
        const float dy = g_off[(b * 18 + 2 * k) * HW + hw0 + ps];
        const float dx = g_off[(b * 18 + 2 * k + 1) * HW + hw0 + ps];
        const float m  = g_mask[(b * 9 + k) * HW + hw0 + ps];
        const float py = (float)(h - 1 + k / 3) + dy;
        const float px = (float)(ps - 1 + k % 3) + dx;
        const float y0f = floorf(py), x0f = floorf(px);
        const float wy1 = py - y0f, wx1 = px - x0f;
        const float wy0 = 1.f - wy1, wx0 = 1.f - wx1;
        const int y0 = (int)y0f, x0 = (int)x0f;
        const int y1 = y0 + 1,  x1 = x0 + 1;
        const float vy0 = ((unsigned)y0 < 128u) ? 1.f : 0.f;
        const float vy1 = ((unsigned)y1 < 128u) ? 1.f : 0.f;
        const float vx0 = ((unsigned)x0 < 128u) ? 1.f : 0.f;
        const float vx1 = ((unsigned)x1 < 128u) ? 1.f : 0.f;
        const int y0c = min(max(y0, 0), 127), y1c = min(max(y1, 0), 127);
        const int x0c = min(max(x0, 0), 127), x1c = min(max(x1, 0), 127);
        const float W00 = wy0 * wx0 * m * vy0 * vx0;
        const float W01 = wy0 * wx1 * m * vy0 * vx1;
        const float W10 = wy1 * wx0 * m * vy1 * vx0;
        const float W11 = wy1 * wx1 * m * vy1 * vx1;
        const int o00 = (y0c << 7) + x0c, o01 = (y0c << 7) + x1c;
        const int o10 = (y1c << 7) + x0c, o11 = (y1c << 7) + x1c;

        // sample 32 channels into ping-pong buffer (STS.128, conflict-free)
        char* Abuf = dgen + ((k & 1) << 15);
#pragma unroll
        for (int g = 0; g < 4; g++) {
            unsigned wh[4], wl[4];
#pragma unroll
            for (int u = 0; u < 4; u++) {
                const int c = (c0 << 5) + (g << 3) + (u << 1);
                const float* p0 = xb + (c << 14);
                const float* p1 = p0 + 16384;
                const float s0 = W00 * p0[o00] + W01 * p0[o01]
                               + W10 * p0[o10] + W11 * p0[o11];
                const float s1 = W00 * p1[o00] + W01 * p1[o01]
                               + W10 * p1[o10] + W11 * p1[o11];
                split2(s0, s1, wh[u], wl[u]);
            }
            const int addr = swz((ps << 7) + (c0 << 6) + (g << 4));
            *(uint4*)(Abuf + addr) = make_uint4(wh[0], wh[1], wh[2], wh[3]);
            *(uint4*)(Abuf + 16384 + addr) = make_uint4(wl[0], wl[1], wl[2], wl[3]);
        }
        __syncthreads();   // the ONLY sync per tap

        // GEMM: C[32p x 32o] += S * W^T (hi/lo split), B frags via LDG
        const unsigned aH = uA + ((k & 1) << 15);
        const unsigned aL = aH + 16384;
        const uint4* bk = g_Bfrag + ((k * 2 + wo) << 9) + lane;
#pragma unroll
        for (int ks = 0; ks < 4; ks++) {
            uint4 bf[4];
#pragma unroll
            for (int nt = 0; nt < 4; nt++) bf[nt] = bk[(ks * 4 + nt) << 5];
#pragma unroll
            for (int mt = 0; mt < 2; mt++) {
                unsigned Af[4], Alf[4];
                const unsigned ad =
                    swz((m0 + mt * 16 + arl) * 128 + (ks * 2 + akc) * 16);
                ldx4(Af, aH + ad);
                ldx4(Alf, aL + ad);
#pragma unroll
                for (int nt = 0; nt < 4; nt++) {
                    mma_bf16(C[mt][nt], Af, bf[nt].x, bf[nt].y);
                    mma_bf16(C[mt][nt], Af, bf[nt].z, bf[nt].w);
                    mma_bf16(C[mt][nt], Alf, bf[nt].x, bf[nt].y);
                }
            }
        }
    }

    // epilogue: transpose to S[64o][132p] (+bias), then coalesced stores
    __syncthreads();
    float* S = (float*)dgen;
    const int prow = lane >> 2;
    const int oc = 2 * (lane & 3);
#pragma unroll
    for (int mt = 0; mt < 2; mt++)
#pragma unroll
        for (int nt = 0; nt < 4; nt++)
#pragma unroll
            for (int q = 0; q < 4; q++) {
                const int p = m0 + mt * 16 + prow + ((q >> 1) << 3);
                const int o = o0 + nt * 8 + oc + (q & 1);
                S[o * 132 + p] = C[mt][nt][q] + sbias[o];
            }
    __syncthreads();
    float* ob = out + (b << 20) + hw0;
#pragma unroll
    for (int j = 0; j < 8; j++) {
        const int f4 = j * 256 + tid;
        const int o = f4 >> 5, p4 = f4 & 31;
        *(float4*)(ob + (o << 14) + p4 * 4) = *(float4*)(S + o * 132 + p4 * 4);
    }
}

// ---------------------------------------------------------------------------
extern "C" void kernel_launch(void* const* d_in, const int* in_sizes, int n_in,
                              void* d_out, int out_size) {
    const float* x      = (const float*)d_in[0];
    const float* w_off  = (const float*)d_in[1];
    const float* b_off  = (const float*)d_in[2];
    const float* w_mask = (const float*)d_in[3];
    const float* b_mask = (const float*)d_in[4];
    const float* w_dcn  = (const float*)d_in[5];
    const float* b_dcn  = (const float*)d_in[6];
    float* out = (float*)d_out;

    cudaFuncSetAttribute(k_offmask, cudaFuncAttributeMaxDynamicSharedMemorySize, SMEM_OM);
    cudaFuncSetAttribute(k_dcn,     cudaFuncAttributeMaxDynamicSharedMemorySize, SMEM2);

    k_prep<<<(9 * 1024 + 9 * 512 + 255) / 256, 256>>>(w_dcn, w_off, w_mask);
    k_offmask<<<Bb * 128, 256, SMEM_OM>>>(x, b_off, b_mask);
    k_dcn<<<Bb * 128, 256, SMEM2>>>(x, b_dcn, out);
}